// round 14
// baseline (speedup 1.0000x reference)
#include <cuda_runtime.h>
#include <cstdint>

#define L_SEQ   2048
#define D_DIM   512
#define B_BATCH 32
#define M_ROWS  (B_BATCH * L_SEQ)   /* 65536 */
#define K_DIM   1024
#define N_DIM   512

// ---------------- scratch (static device globals: no allocation) ----------------
__device__ float g_ycat[(size_t)M_ROWS * K_DIM];   // 256 MiB: [y_conv | y_auto] (tf32-rounded)
__device__ float g_wr[(size_t)N_DIM * K_DIM];      // tf32-rounded proj_w
__device__ float g_xm[M_ROWS];
__device__ float g_w5[B_BATCH * 5];
__device__ int   g_lag5[B_BATCH * 5];

__device__ __forceinline__ uint32_t smem_to_u32(const void* p) {
    uint32_t a;
    asm("{ .reg .u64 t; cvta.to.shared.u64 t, %1; cvt.u32.u64 %0, t; }" : "=r"(a) : "l"(p));
    return a;
}
__device__ __forceinline__ float t32(float f) {
    uint32_t r; asm("cvt.rna.tf32.f32 %0, %1;" : "=r"(r) : "f"(f));
    return __uint_as_float(r);
}

// Candidate lag i of np.linspace(1,168,32).astype(int64)
__device__ __forceinline__ int lag_of(int i) {
    if (i == 31) return 168;
    return (int)(1.0 + (double)i * (167.0 / 31.0));
}

// =================== Kernel 1: xm[b,l] = mean_d x[b,l,d] ===================
__global__ __launch_bounds__(256) void mean_kernel(const float* __restrict__ x) {
    int row  = blockIdx.x * 8 + (threadIdx.x >> 5);
    int lane = threadIdx.x & 31;
    const float4* xr = (const float4*)(x + (size_t)row * D_DIM);
    float s = 0.f;
#pragma unroll
    for (int q = 0; q < 4; q++) {
        float4 v = xr[q * 32 + lane];
        s += v.x + v.y + v.z + v.w;
    }
#pragma unroll
    for (int o = 16; o; o >>= 1) s += __shfl_down_sync(0xffffffffu, s, o);
    if (lane == 0) g_xm[row] = s * (1.0f / 512.0f);
}

// =============== Kernel 2: per-batch lag scores, top-5 weights ===============
__global__ __launch_bounds__(256) void scores_kernel() {
    __shared__ float s[L_SEQ];
    __shared__ float sc[32];
    int b = blockIdx.x, tid = threadIdx.x;
    for (int i = tid; i < L_SEQ; i += 256) s[i] = g_xm[b * L_SEQ + i];
    __syncthreads();
    int warp = tid >> 5, lane = tid & 31;
#pragma unroll
    for (int j = 0; j < 4; j++) {
        int li = warp * 4 + j;
        int lag = lag_of(li);
        float p = 0.f;
        for (int t = lane; t < L_SEQ - lag; t += 32) p += s[t] * s[t + lag];
#pragma unroll
        for (int o = 16; o; o >>= 1) p += __shfl_down_sync(0xffffffffu, p, o);
        if (lane == 0) sc[li] = p / (float)(L_SEQ - lag);
    }
    __syncthreads();
    if (tid == 0) {
        bool used[32];
        for (int i = 0; i < 32; i++) used[i] = false;
        float vals[5]; int idx[5];
        for (int p = 0; p < 5; p++) {
            float best = -3.4e38f; int bi = 0;
            for (int i = 0; i < 32; i++)
                if (!used[i] && sc[i] > best) { best = sc[i]; bi = i; }
            used[bi] = true; vals[p] = best; idx[p] = bi;
        }
        float denom = vals[0] + vals[1] + vals[2] + vals[3] + vals[4] + 1e-6f;
        for (int p = 0; p < 5; p++) {
            g_w5[b * 5 + p]   = vals[p] / denom;
            g_lag5[b * 5 + p] = lag_of(idx[p]);
        }
    }
}

// =============== Kernel 2b: round proj_w to tf32 (rna) ===============
__global__ __launch_bounds__(256) void wround_kernel(const float* __restrict__ w) {
    size_t i = (size_t)blockIdx.x * 1024 + (size_t)threadIdx.x * 4;
    float4 v = *(const float4*)(w + i);
    *(float4*)(g_wr + i) = make_float4(t32(v.x), t32(v.y), t32(v.z), t32(v.w));
}

// =============== Kernel 3: build ycat = [y_conv | y_auto] (tf32-rounded) ===============
__global__ __launch_bounds__(256) void ycat_kernel(
    const float* __restrict__ x,  const float* __restrict__ w0,
    const float* __restrict__ w1, const float* __restrict__ w2)
{
    const int OFF[11] = {-12, -8, -4, -2, -1, 0, 1, 2, 4, 8, 12};
    int b  = blockIdx.x >> 6;
    int lt = (blockIdx.x & 63) << 5;
    int tid = threadIdx.x;
    int d  = (tid & 127) << 2;
    int rh = tid >> 7;

    float cf[11][4];
#pragma unroll
    for (int c = 0; c < 4; c++) {
        int dd = d + c;
        float a0 = w0[dd * 3 + 0], a1 = w0[dd * 3 + 1], a2 = w0[dd * 3 + 2];
        float e0 = w1[dd * 5 + 0], e1 = w1[dd * 5 + 1], e2 = w1[dd * 5 + 2],
              e3 = w1[dd * 5 + 3], e4 = w1[dd * 5 + 4];
        float f0 = w2[dd * 7 + 0], f1 = w2[dd * 7 + 1], f2 = w2[dd * 7 + 2],
              f3 = w2[dd * 7 + 3], f4 = w2[dd * 7 + 4], f5 = w2[dd * 7 + 5],
              f6 = w2[dd * 7 + 6];
        cf[0][c]  = f0;            cf[1][c]  = f1;            cf[2][c]  = e0 + f2;
        cf[3][c]  = e1;            cf[4][c]  = a0;            cf[5][c]  = a1 + e2 + f3;
        cf[6][c]  = a2;            cf[7][c]  = e3;            cf[8][c]  = e4 + f4;
        cf[9][c]  = f5;            cf[10][c] = f6;
    }
    float aw[5]; int al[5];
#pragma unroll
    for (int j = 0; j < 5; j++) { aw[j] = g_w5[b * 5 + j]; al[j] = g_lag5[b * 5 + j]; }

    const float* xb = x + ((size_t)b * L_SEQ) * D_DIM;
    for (int lidx = rh; lidx < 32; lidx += 2) {
        int l = lt + lidx;
        float ax = 0.f, ay = 0.f, az = 0.f, aq = 0.f;
#pragma unroll
        for (int o = 0; o < 11; o++) {
            int ll = l + OFF[o];
            if (ll >= 0 && ll < L_SEQ) {
                float4 xv = *(const float4*)(xb + (size_t)ll * D_DIM + d);
                ax += cf[o][0] * xv.x; ay += cf[o][1] * xv.y;
                az += cf[o][2] * xv.z; aq += cf[o][3] * xv.w;
            }
        }
        float ux = 0.f, uy = 0.f, uz = 0.f, uq = 0.f;
#pragma unroll
        for (int j = 0; j < 5; j++) {
            int ll = l - al[j]; if (ll < 0) ll += L_SEQ;
            float4 xv = *(const float4*)(xb + (size_t)ll * D_DIM + d);
            ux += aw[j] * xv.x; uy += aw[j] * xv.y;
            uz += aw[j] * xv.z; uq += aw[j] * xv.w;
        }
        size_t row = (size_t)b * L_SEQ + l;
        *(float4*)(g_ycat + row * K_DIM + d) =
            make_float4(t32(ax), t32(ay), t32(az), t32(aq));
        *(float4*)(g_ycat + row * K_DIM + 512 + d) =
            make_float4(t32(ux), t32(uy), t32(uz), t32(uq));
    }
}

// =============== Kernel 4: tf32 mma.sync GEMM, 128x128 block, 64x64 warp tile ===============
// 3-stage cp.async pipeline; operands pre-rounded to tf32 so staging is a raw copy.
#define BK 16
#define ROW_W 20                        /* padded row stride (words): conflict-free */
#define TILE_WORDS (128 * ROW_W)        /* 2560 words per A or B stage */
#define STAGE_WORDS (2 * TILE_WORDS)    /* A then B */
#define GEMM_SMEM (3 * STAGE_WORDS * 4) /* 61440 B */

__global__ void __launch_bounds__(128, 2) gemm_sm_kernel(
    const float* __restrict__ x, const float* __restrict__ bias, float* __restrict__ out)
{
    extern __shared__ uint32_t sm[];
    const int tid  = threadIdx.x;
    const int warp = tid >> 5, lane = tid & 31;
    const int gg = lane >> 2, tg = lane & 3;
    const int wm = (warp & 1) << 6;       // 2 warps along M
    const int wn = (warp >> 1) << 6;      // 2 warps along N, 64 wide each
    const int n0 = (int)(blockIdx.x & 3) << 7;   // n fastest: A tile L2-shared by 4 CTAs
    const int m0 = (int)(blockIdx.x >> 2) << 7;

    const float* Ag = g_ycat + (size_t)m0 * K_DIM;
    const float* Bg = g_wr   + (size_t)n0 * K_DIM;

    const uint32_t sbase = smem_to_u32(sm);
    const int r  = tid >> 2;              // staging row 0..31 (+32j)
    const int c4 = (tid & 3) << 2;        // staging col 0,4,8,12

    float acc[4][8][4];
#pragma unroll
    for (int mi = 0; mi < 4; mi++)
#pragma unroll
        for (int ni = 0; ni < 8; ni++)
#pragma unroll
            for (int q = 0; q < 4; q++) acc[mi][ni][q] = 0.f;

    auto stage_load = [&](int kt, int s) {
        const float* ag = Ag + kt * BK;
        const float* bg = Bg + kt * BK;
        uint32_t sa = sbase + (uint32_t)(s * STAGE_WORDS) * 4u;
        uint32_t sb = sa + TILE_WORDS * 4u;
#pragma unroll
        for (int j = 0; j < 4; j++) {
            int rr = r + (j << 5);
            uint32_t off = (uint32_t)(rr * ROW_W + c4) * 4u;
            asm volatile("cp.async.cg.shared.global [%0], [%1], 16;"
                         :: "r"(sa + off), "l"(ag + (size_t)rr * K_DIM + c4));
            asm volatile("cp.async.cg.shared.global [%0], [%1], 16;"
                         :: "r"(sb + off), "l"(bg + (size_t)rr * K_DIM + c4));
        }
        asm volatile("cp.async.commit_group;" ::: "memory");
    };

    stage_load(0, 0); stage_load(1, 1); stage_load(2, 2);

#pragma unroll 1
    for (int kt = 0; kt < 64; kt++) {
        const int s = kt % 3;
        asm volatile("cp.async.wait_group 2;" ::: "memory");
        __syncthreads();
        const uint32_t* As = sm + s * STAGE_WORDS;
        const uint32_t* Bs = As + TILE_WORDS;
#pragma unroll
        for (int ks = 0; ks < 2; ks++) {
            const int kk = ks << 3;
            uint32_t a[4][4], b[8][2];
#pragma unroll
            for (int mi = 0; mi < 4; mi++) {
                int rr = wm + (mi << 4) + gg;
                a[mi][0] = As[rr * ROW_W + kk + tg];
                a[mi][1] = As[(rr + 8) * ROW_W + kk + tg];
                a[mi][2] = As[rr * ROW_W + kk + tg + 4];
                a[mi][3] = As[(rr + 8) * ROW_W + kk + tg + 4];
            }
#pragma unroll
            for (int ni = 0; ni < 8; ni++) {
                int cc = wn + (ni << 3) + gg;
                b[ni][0] = Bs[cc * ROW_W + kk + tg];
                b[ni][1] = Bs[cc * ROW_W + kk + tg + 4];
            }
#pragma unroll
            for (int mi = 0; mi < 4; mi++)
#pragma unroll
                for (int ni = 0; ni < 8; ni++)
                    asm volatile(
                        "mma.sync.aligned.m16n8k8.row.col.f32.tf32.tf32.f32 "
                        "{%0,%1,%2,%3}, {%4,%5,%6,%7}, {%8,%9}, {%0,%1,%2,%3};\n"
                        : "+f"(acc[mi][ni][0]), "+f"(acc[mi][ni][1]),
                          "+f"(acc[mi][ni][2]), "+f"(acc[mi][ni][3])
                        : "r"(a[mi][0]), "r"(a[mi][1]), "r"(a[mi][2]), "r"(a[mi][3]),
                          "r"(b[ni][0]), "r"(b[ni][1]));
        }
        __syncthreads();
        if (kt + 3 < 64) stage_load(kt + 3, s);
        else asm volatile("cp.async.commit_group;" ::: "memory");  // keep group count aligned
    }

    // epilogue: h = gemm + bias + x
#pragma unroll
    for (int mi = 0; mi < 4; mi++) {
        int row = m0 + wm + (mi << 4) + gg;
#pragma unroll
        for (int ni = 0; ni < 8; ni++) {
            int col = n0 + wn + (ni << 3) + (tg << 1);
            float bz0 = bias[col], bz1 = bias[col + 1];
            float2 x0 = *(const float2*)(x + (size_t)row * N_DIM + col);
            float2 x1 = *(const float2*)(x + (size_t)(row + 8) * N_DIM + col);
            float2 o0 = make_float2(acc[mi][ni][0] + bz0 + x0.x, acc[mi][ni][1] + bz1 + x0.y);
            float2 o1 = make_float2(acc[mi][ni][2] + bz0 + x1.x, acc[mi][ni][3] + bz1 + x1.y);
            *(float2*)(out + (size_t)row * N_DIM + col)       = o0;
            *(float2*)(out + (size_t)(row + 8) * N_DIM + col) = o1;
        }
    }
}

// =============== Kernel 5: LayerNorm over D, in place on out ===============
__global__ __launch_bounds__(256) void ln_kernel(
    float* __restrict__ out, const float* __restrict__ gam, const float* __restrict__ bet)
{
    int row  = blockIdx.x * 8 + (threadIdx.x >> 5);
    int lane = threadIdx.x & 31;
    float4* o4 = (float4*)(out + (size_t)row * D_DIM);
    float4 v[4];
    float s = 0.f, s2 = 0.f;
#pragma unroll
    for (int q = 0; q < 4; q++) {
        v[q] = o4[q * 32 + lane];
        s  += v[q].x + v[q].y + v[q].z + v[q].w;
        s2 += v[q].x * v[q].x + v[q].y * v[q].y + v[q].z * v[q].z + v[q].w * v[q].w;
    }
#pragma unroll
    for (int o = 16; o; o >>= 1) {
        s  += __shfl_xor_sync(0xffffffffu, s, o);
        s2 += __shfl_xor_sync(0xffffffffu, s2, o);
    }
    float mu  = s * (1.0f / 512.0f);
    float var = s2 * (1.0f / 512.0f) - mu * mu;
    float inv = rsqrtf(var + 1e-5f);
    const float4* g4 = (const float4*)gam;
    const float4* b4 = (const float4*)bet;
#pragma unroll
    for (int q = 0; q < 4; q++) {
        float4 gv = g4[q * 32 + lane], bv = b4[q * 32 + lane];
        float4 r;
        r.x = (v[q].x - mu) * inv * gv.x + bv.x;
        r.y = (v[q].y - mu) * inv * gv.y + bv.y;
        r.z = (v[q].z - mu) * inv * gv.z + bv.z;
        r.w = (v[q].w - mu) * inv * gv.w + bv.w;
        o4[q * 32 + lane] = r;
    }
}

// ============================== launch ==============================
extern "C" void kernel_launch(void* const* d_in, const int* in_sizes, int n_in,
                              void* d_out, int out_size) {
    const float* x   = (const float*)d_in[0];
    const float* cw0 = (const float*)d_in[1];
    const float* cw1 = (const float*)d_in[2];
    const float* cw2 = (const float*)d_in[3];
    const float* pw  = (const float*)d_in[4];
    const float* pb  = (const float*)d_in[5];
    const float* lng = (const float*)d_in[6];
    const float* lnb = (const float*)d_in[7];
    float* out = (float*)d_out;

    cudaFuncSetAttribute(gemm_sm_kernel,
                         cudaFuncAttributeMaxDynamicSharedMemorySize, GEMM_SMEM);

    mean_kernel<<<M_ROWS / 8, 256>>>(x);
    scores_kernel<<<B_BATCH, 256>>>();
    wround_kernel<<<(N_DIM * K_DIM) / 1024, 256>>>(pw);
    ycat_kernel<<<B_BATCH * (L_SEQ / 32), 256>>>(x, cw0, cw1, cw2);
    gemm_sm_kernel<<<(M_ROWS / 128) * (N_DIM / 128), 128, GEMM_SMEM>>>(x, pb, out);
    ln_kernel<<<M_ROWS / 8, 256>>>(out, lng, lnb);
}

// round 15
// speedup vs baseline: 1.7594x; 1.7594x over previous
#include <cuda_runtime.h>
#include <cuda_fp16.h>
#include <cstdint>

#define L_SEQ   2048
#define D_DIM   512
#define B_BATCH 32
#define M_ROWS  (B_BATCH * L_SEQ)   /* 65536 */
#define K_DIM   1024
#define N_DIM   512

// ---------------- scratch (static device globals: no allocation) ----------------
__device__ __half g_ych[(size_t)M_ROWS * K_DIM];   // 128 MiB: [y_conv | y_auto] in fp16
__device__ __half g_wh[(size_t)N_DIM * K_DIM];     // fp16 proj_w
__device__ float g_xm[M_ROWS];
__device__ float g_w5[B_BATCH * 5];
__device__ int   g_lag5[B_BATCH * 5];

__device__ __forceinline__ uint32_t smem_to_u32(const void* p) {
    uint32_t a;
    asm("{ .reg .u64 t; cvta.to.shared.u64 t, %1; cvt.u32.u64 %0, t; }" : "=r"(a) : "l"(p));
    return a;
}
__device__ __forceinline__ uint32_t pack_h2(float a, float b) {
    __half2 h = __floats2half2_rn(a, b);
    return *(uint32_t*)&h;
}

// Candidate lag i of np.linspace(1,168,32).astype(int64)
__device__ __forceinline__ int lag_of(int i) {
    if (i == 31) return 168;
    return (int)(1.0 + (double)i * (167.0 / 31.0));
}

// =================== Kernel 1: xm[b,l] = mean_d x[b,l,d] ===================
__global__ __launch_bounds__(256) void mean_kernel(const float* __restrict__ x) {
    int row  = blockIdx.x * 8 + (threadIdx.x >> 5);
    int lane = threadIdx.x & 31;
    const float4* xr = (const float4*)(x + (size_t)row * D_DIM);
    float s = 0.f;
#pragma unroll
    for (int q = 0; q < 4; q++) {
        float4 v = xr[q * 32 + lane];
        s += v.x + v.y + v.z + v.w;
    }
#pragma unroll
    for (int o = 16; o; o >>= 1) s += __shfl_down_sync(0xffffffffu, s, o);
    if (lane == 0) g_xm[row] = s * (1.0f / 512.0f);
}

// =============== Kernel 2: per-batch lag scores, top-5 weights ===============
__global__ __launch_bounds__(256) void scores_kernel() {
    __shared__ float s[L_SEQ];
    __shared__ float sc[32];
    int b = blockIdx.x, tid = threadIdx.x;
    for (int i = tid; i < L_SEQ; i += 256) s[i] = g_xm[b * L_SEQ + i];
    __syncthreads();
    int warp = tid >> 5, lane = tid & 31;
#pragma unroll
    for (int j = 0; j < 4; j++) {
        int li = warp * 4 + j;
        int lag = lag_of(li);
        float p = 0.f;
        for (int t = lane; t < L_SEQ - lag; t += 32) p += s[t] * s[t + lag];
#pragma unroll
        for (int o = 16; o; o >>= 1) p += __shfl_down_sync(0xffffffffu, p, o);
        if (lane == 0) sc[li] = p / (float)(L_SEQ - lag);
    }
    __syncthreads();
    if (tid == 0) {
        bool used[32];
        for (int i = 0; i < 32; i++) used[i] = false;
        float vals[5]; int idx[5];
        for (int p = 0; p < 5; p++) {
            float best = -3.4e38f; int bi = 0;
            for (int i = 0; i < 32; i++)
                if (!used[i] && sc[i] > best) { best = sc[i]; bi = i; }
            used[bi] = true; vals[p] = best; idx[p] = bi;
        }
        float denom = vals[0] + vals[1] + vals[2] + vals[3] + vals[4] + 1e-6f;
        for (int p = 0; p < 5; p++) {
            g_w5[b * 5 + p]   = vals[p] / denom;
            g_lag5[b * 5 + p] = lag_of(idx[p]);
        }
    }
}

// =============== Kernel 2b: proj_w -> fp16 ===============
__global__ __launch_bounds__(256) void whalf_kernel(const float* __restrict__ w) {
    size_t i = (size_t)blockIdx.x * 1024 + (size_t)threadIdx.x * 4;
    float4 v = *(const float4*)(w + i);
    *(uint2*)(g_wh + i) = make_uint2(pack_h2(v.x, v.y), pack_h2(v.z, v.w));
}

// =============== Kernel 3: build ycat = [y_conv | y_auto] (fp16) ===============
__global__ __launch_bounds__(256) void ycat_kernel(
    const float* __restrict__ x,  const float* __restrict__ w0,
    const float* __restrict__ w1, const float* __restrict__ w2)
{
    const int OFF[11] = {-12, -8, -4, -2, -1, 0, 1, 2, 4, 8, 12};
    int b  = blockIdx.x >> 6;
    int lt = (blockIdx.x & 63) << 5;
    int tid = threadIdx.x;
    int d  = (tid & 127) << 2;
    int rh = tid >> 7;

    float cf[11][4];
#pragma unroll
    for (int c = 0; c < 4; c++) {
        int dd = d + c;
        float a0 = w0[dd * 3 + 0], a1 = w0[dd * 3 + 1], a2 = w0[dd * 3 + 2];
        float e0 = w1[dd * 5 + 0], e1 = w1[dd * 5 + 1], e2 = w1[dd * 5 + 2],
              e3 = w1[dd * 5 + 3], e4 = w1[dd * 5 + 4];
        float f0 = w2[dd * 7 + 0], f1 = w2[dd * 7 + 1], f2 = w2[dd * 7 + 2],
              f3 = w2[dd * 7 + 3], f4 = w2[dd * 7 + 4], f5 = w2[dd * 7 + 5],
              f6 = w2[dd * 7 + 6];
        cf[0][c]  = f0;            cf[1][c]  = f1;            cf[2][c]  = e0 + f2;
        cf[3][c]  = e1;            cf[4][c]  = a0;            cf[5][c]  = a1 + e2 + f3;
        cf[6][c]  = a2;            cf[7][c]  = e3;            cf[8][c]  = e4 + f4;
        cf[9][c]  = f5;            cf[10][c] = f6;
    }
    float aw[5]; int al[5];
#pragma unroll
    for (int j = 0; j < 5; j++) { aw[j] = g_w5[b * 5 + j]; al[j] = g_lag5[b * 5 + j]; }

    const float* xb = x + ((size_t)b * L_SEQ) * D_DIM;
    for (int lidx = rh; lidx < 32; lidx += 2) {
        int l = lt + lidx;
        float ax = 0.f, ay = 0.f, az = 0.f, aq = 0.f;
#pragma unroll
        for (int o = 0; o < 11; o++) {
            int ll = l + OFF[o];
            if (ll >= 0 && ll < L_SEQ) {
                float4 xv = *(const float4*)(xb + (size_t)ll * D_DIM + d);
                ax += cf[o][0] * xv.x; ay += cf[o][1] * xv.y;
                az += cf[o][2] * xv.z; aq += cf[o][3] * xv.w;
            }
        }
        float ux = 0.f, uy = 0.f, uz = 0.f, uq = 0.f;
#pragma unroll
        for (int j = 0; j < 5; j++) {
            int ll = l - al[j]; if (ll < 0) ll += L_SEQ;
            float4 xv = *(const float4*)(xb + (size_t)ll * D_DIM + d);
            ux += aw[j] * xv.x; uy += aw[j] * xv.y;
            uz += aw[j] * xv.z; uq += aw[j] * xv.w;
        }
        size_t row = (size_t)b * L_SEQ + l;
        *(uint2*)(g_ych + row * K_DIM + d) =
            make_uint2(pack_h2(ax, ay), pack_h2(az, aq));
        *(uint2*)(g_ych + row * K_DIM + 512 + d) =
            make_uint2(pack_h2(ux, uy), pack_h2(uz, uq));
    }
}

// =============== Kernel 4: fp16 mma.sync m16n8k16 GEMM, 128x128 block, 64x64 warp ===============
// BK=32, 3-stage cp.async pipeline, ldmatrix fragment loads.
#define BK 32
#define ROW_H 20                        /* words per 32-half row (16 data + 4 pad) */
#define TILE_W (128 * ROW_H)            /* words per A or B tile: 2560 */
#define STG_W  (2 * TILE_W)
#define GEMM_SMEM (3 * STG_W * 4)       /* 61440 B */

__global__ void __launch_bounds__(128, 2) gemm_fp16_kernel(
    const float* __restrict__ x, const float* __restrict__ bias, float* __restrict__ out)
{
    extern __shared__ uint32_t sm[];
    const int tid  = threadIdx.x;
    const int warp = tid >> 5, lane = tid & 31;
    const int gg = lane >> 2, tg = lane & 3;
    const int wm = (warp & 1) << 6;       // 2 warps along M
    const int wn = (warp >> 1) << 6;      // 2 warps along N
    const int n0 = (int)(blockIdx.x & 3) << 7;   // n fastest: A tile L2-shared by 4 CTAs
    const int m0 = (int)(blockIdx.x >> 2) << 7;

    const __half* Ag = g_ych + (size_t)m0 * K_DIM;
    const __half* Bg = g_wh  + (size_t)n0 * K_DIM;

    const uint32_t sbase = smem_to_u32(sm);
    const int r  = tid >> 2;              // staging row 0..31 (+32j)
    const int c4 = tid & 3;               // staging 16B-chunk 0..3

    // ldmatrix lane-address components
    const int rA = wm + (lane & 7) + ((lane >> 3) & 1) * 8;   // A row within tile
    const int wA = ((lane >> 4) & 1) * 4;                     // A k-chunk word
    const int rB = wn + (lane & 7);                           // B n-row
    const int wB = ((lane >> 3) & 1) * 4;                     // B k-chunk word (x2)

    float acc[4][8][4];
#pragma unroll
    for (int mi = 0; mi < 4; mi++)
#pragma unroll
        for (int ni = 0; ni < 8; ni++)
#pragma unroll
            for (int q = 0; q < 4; q++) acc[mi][ni][q] = 0.f;

    auto stage_load = [&](int kt, int s) {
        const __half* ag = Ag + kt * BK;
        const __half* bg = Bg + kt * BK;
        uint32_t sa = sbase + (uint32_t)(s * STG_W) * 4u;
        uint32_t sb = sa + TILE_W * 4u;
#pragma unroll
        for (int j = 0; j < 4; j++) {
            int rr = r + (j << 5);
            uint32_t off = (uint32_t)(rr * ROW_H + c4 * 4) * 4u;
            asm volatile("cp.async.cg.shared.global [%0], [%1], 16;"
                         :: "r"(sa + off), "l"(ag + (size_t)rr * K_DIM + c4 * 8));
            asm volatile("cp.async.cg.shared.global [%0], [%1], 16;"
                         :: "r"(sb + off), "l"(bg + (size_t)rr * K_DIM + c4 * 8));
        }
        asm volatile("cp.async.commit_group;" ::: "memory");
    };

    stage_load(0, 0); stage_load(1, 1); stage_load(2, 2);

#pragma unroll 1
    for (int kt = 0; kt < 32; kt++) {
        const int s = kt % 3;
        asm volatile("cp.async.wait_group 2;" ::: "memory");
        __syncthreads();
        const uint32_t abase = sbase + (uint32_t)(s * STG_W) * 4u;
        const uint32_t bbase = abase + TILE_W * 4u;
#pragma unroll
        for (int ks = 0; ks < 2; ks++) {
            uint32_t a[4][4], b[8][2];
#pragma unroll
            for (int mi = 0; mi < 4; mi++) {
                uint32_t ad = abase + (uint32_t)((rA + mi * 16) * ROW_H + wA + ks * 8) * 4u;
                asm volatile("ldmatrix.sync.aligned.m8n8.x4.shared.b16 {%0,%1,%2,%3}, [%4];"
                             : "=r"(a[mi][0]), "=r"(a[mi][1]), "=r"(a[mi][2]), "=r"(a[mi][3])
                             : "r"(ad));
            }
#pragma unroll
            for (int ni = 0; ni < 8; ni++) {
                uint32_t bd = bbase + (uint32_t)((rB + ni * 8) * ROW_H + wB + ks * 8) * 4u;
                asm volatile("ldmatrix.sync.aligned.m8n8.x2.shared.b16 {%0,%1}, [%2];"
                             : "=r"(b[ni][0]), "=r"(b[ni][1]) : "r"(bd));
            }
#pragma unroll
            for (int mi = 0; mi < 4; mi++)
#pragma unroll
                for (int ni = 0; ni < 8; ni++)
                    asm volatile(
                        "mma.sync.aligned.m16n8k16.row.col.f32.f16.f16.f32 "
                        "{%0,%1,%2,%3}, {%4,%5,%6,%7}, {%8,%9}, {%0,%1,%2,%3};\n"
                        : "+f"(acc[mi][ni][0]), "+f"(acc[mi][ni][1]),
                          "+f"(acc[mi][ni][2]), "+f"(acc[mi][ni][3])
                        : "r"(a[mi][0]), "r"(a[mi][1]), "r"(a[mi][2]), "r"(a[mi][3]),
                          "r"(b[ni][0]), "r"(b[ni][1]));
        }
        __syncthreads();
        if (kt + 3 < 32) stage_load(kt + 3, s);
        else asm volatile("cp.async.commit_group;" ::: "memory");  // keep group count aligned
    }

    // epilogue: h = gemm + bias + x
#pragma unroll
    for (int mi = 0; mi < 4; mi++) {
        int row = m0 + wm + (mi << 4) + gg;
#pragma unroll
        for (int ni = 0; ni < 8; ni++) {
            int col = n0 + wn + (ni << 3) + (tg << 1);
            float bz0 = bias[col], bz1 = bias[col + 1];
            float2 x0 = *(const float2*)(x + (size_t)row * N_DIM + col);
            float2 x1 = *(const float2*)(x + (size_t)(row + 8) * N_DIM + col);
            float2 o0 = make_float2(acc[mi][ni][0] + bz0 + x0.x, acc[mi][ni][1] + bz1 + x0.y);
            float2 o1 = make_float2(acc[mi][ni][2] + bz0 + x1.x, acc[mi][ni][3] + bz1 + x1.y);
            *(float2*)(out + (size_t)row * N_DIM + col)       = o0;
            *(float2*)(out + (size_t)(row + 8) * N_DIM + col) = o1;
        }
    }
}

// =============== Kernel 5: LayerNorm over D, in place on out ===============
__global__ __launch_bounds__(256) void ln_kernel(
    float* __restrict__ out, const float* __restrict__ gam, const float* __restrict__ bet)
{
    int row  = blockIdx.x * 8 + (threadIdx.x >> 5);
    int lane = threadIdx.x & 31;
    float4* o4 = (float4*)(out + (size_t)row * D_DIM);
    float4 v[4];
    float s = 0.f, s2 = 0.f;
#pragma unroll
    for (int q = 0; q < 4; q++) {
        v[q] = o4[q * 32 + lane];
        s  += v[q].x + v[q].y + v[q].z + v[q].w;
        s2 += v[q].x * v[q].x + v[q].y * v[q].y + v[q].z * v[q].z + v[q].w * v[q].w;
    }
#pragma unroll
    for (int o = 16; o; o >>= 1) {
        s  += __shfl_xor_sync(0xffffffffu, s, o);
        s2 += __shfl_xor_sync(0xffffffffu, s2, o);
    }
    float mu  = s * (1.0f / 512.0f);
    float var = s2 * (1.0f / 512.0f) - mu * mu;
    float inv = rsqrtf(var + 1e-5f);
    const float4* g4 = (const float4*)gam;
    const float4* b4 = (const float4*)bet;
#pragma unroll
    for (int q = 0; q < 4; q++) {
        float4 gv = g4[q * 32 + lane], bv = b4[q * 32 + lane];
        float4 r;
        r.x = (v[q].x - mu) * inv * gv.x + bv.x;
        r.y = (v[q].y - mu) * inv * gv.y + bv.y;
        r.z = (v[q].z - mu) * inv * gv.z + bv.z;
        r.w = (v[q].w - mu) * inv * gv.w + bv.w;
        o4[q * 32 + lane] = r;
    }
}

// ============================== launch ==============================
extern "C" void kernel_launch(void* const* d_in, const int* in_sizes, int n_in,
                              void* d_out, int out_size) {
    const float* x   = (const float*)d_in[0];
    const float* cw0 = (const float*)d_in[1];
    const float* cw1 = (const float*)d_in[2];
    const float* cw2 = (const float*)d_in[3];
    const float* pw  = (const float*)d_in[4];
    const float* pb  = (const float*)d_in[5];
    const float* lng = (const float*)d_in[6];
    const float* lnb = (const float*)d_in[7];
    float* out = (float*)d_out;

    cudaFuncSetAttribute(gemm_fp16_kernel,
                         cudaFuncAttributeMaxDynamicSharedMemorySize, GEMM_SMEM);

    mean_kernel<<<M_ROWS / 8, 256>>>(x);
    scores_kernel<<<B_BATCH, 256>>>();
    whalf_kernel<<<(N_DIM * K_DIM) / 1024, 256>>>(pw);
    ycat_kernel<<<B_BATCH * (L_SEQ / 32), 256>>>(x, cw0, cw1, cw2);
    gemm_fp16_kernel<<<(M_ROWS / 128) * (N_DIM / 128), 128, GEMM_SMEM>>>(x, pb, out);
    ln_kernel<<<M_ROWS / 8, 256>>>(out, lng, lnb);
}

// round 16
// speedup vs baseline: 1.7766x; 1.0098x over previous
#include <cuda_runtime.h>
#include <cuda_fp16.h>
#include <cstdint>

#define L_SEQ   2048
#define D_DIM   512
#define B_BATCH 32
#define M_ROWS  (B_BATCH * L_SEQ)   /* 65536 */
#define K_DIM   1024
#define N_DIM   512

// ---------------- scratch (static device globals: no allocation) ----------------
__device__ __half g_ych[(size_t)M_ROWS * K_DIM];   // 128 MiB: [y_conv | y_auto] in fp16
__device__ __half g_wh[(size_t)N_DIM * K_DIM];     // fp16 proj_w
__device__ float g_xm[M_ROWS];
__device__ float g_w5[B_BATCH * 5];
__device__ int   g_lag5[B_BATCH * 5];

__device__ __forceinline__ uint32_t smem_to_u32(const void* p) {
    uint32_t a;
    asm("{ .reg .u64 t; cvta.to.shared.u64 t, %1; cvt.u32.u64 %0, t; }" : "=r"(a) : "l"(p));
    return a;
}
__device__ __forceinline__ uint32_t pack_h2(float a, float b) {
    __half2 h = __floats2half2_rn(a, b);
    return *(uint32_t*)&h;
}

// Candidate lag i of np.linspace(1,168,32).astype(int64)
__device__ __forceinline__ int lag_of(int i) {
    if (i == 31) return 168;
    return (int)(1.0 + (double)i * (167.0 / 31.0));
}

// =================== Kernel 1: xm[b,l] = mean_d x[b,l,d] ===================
__global__ __launch_bounds__(256) void mean_kernel(const float* __restrict__ x) {
    int row  = blockIdx.x * 8 + (threadIdx.x >> 5);
    int lane = threadIdx.x & 31;
    const float4* xr = (const float4*)(x + (size_t)row * D_DIM);
    float s = 0.f;
#pragma unroll
    for (int q = 0; q < 4; q++) {
        float4 v = xr[q * 32 + lane];
        s += v.x + v.y + v.z + v.w;
    }
#pragma unroll
    for (int o = 16; o; o >>= 1) s += __shfl_down_sync(0xffffffffu, s, o);
    if (lane == 0) g_xm[row] = s * (1.0f / 512.0f);
}

// =============== Kernel 2: per-batch lag scores, top-5 weights ===============
__global__ __launch_bounds__(256) void scores_kernel() {
    __shared__ float s[L_SEQ];
    __shared__ float sc[32];
    int b = blockIdx.x, tid = threadIdx.x;
    for (int i = tid; i < L_SEQ; i += 256) s[i] = g_xm[b * L_SEQ + i];
    __syncthreads();
    int warp = tid >> 5, lane = tid & 31;
#pragma unroll
    for (int j = 0; j < 4; j++) {
        int li = warp * 4 + j;
        int lag = lag_of(li);
        float p = 0.f;
        for (int t = lane; t < L_SEQ - lag; t += 32) p += s[t] * s[t + lag];
#pragma unroll
        for (int o = 16; o; o >>= 1) p += __shfl_down_sync(0xffffffffu, p, o);
        if (lane == 0) sc[li] = p / (float)(L_SEQ - lag);
    }
    __syncthreads();
    if (tid == 0) {
        bool used[32];
        for (int i = 0; i < 32; i++) used[i] = false;
        float vals[5]; int idx[5];
        for (int p = 0; p < 5; p++) {
            float best = -3.4e38f; int bi = 0;
            for (int i = 0; i < 32; i++)
                if (!used[i] && sc[i] > best) { best = sc[i]; bi = i; }
            used[bi] = true; vals[p] = best; idx[p] = bi;
        }
        float denom = vals[0] + vals[1] + vals[2] + vals[3] + vals[4] + 1e-6f;
        for (int p = 0; p < 5; p++) {
            g_w5[b * 5 + p]   = vals[p] / denom;
            g_lag5[b * 5 + p] = lag_of(idx[p]);
        }
    }
}

// =============== Kernel 2b: proj_w -> fp16 ===============
__global__ __launch_bounds__(256) void whalf_kernel(const float* __restrict__ w) {
    size_t i = (size_t)blockIdx.x * 1024 + (size_t)threadIdx.x * 4;
    float4 v = *(const float4*)(w + i);
    *(uint2*)(g_wh + i) = make_uint2(pack_h2(v.x, v.y), pack_h2(v.z, v.w));
}

// =============== Kernel 3: build ycat = [y_conv | y_auto] (fp16) ===============
__global__ __launch_bounds__(256, 2) void ycat_kernel(
    const float* __restrict__ x,  const float* __restrict__ w0,
    const float* __restrict__ w1, const float* __restrict__ w2)
{
    const int OFF[11] = {-12, -8, -4, -2, -1, 0, 1, 2, 4, 8, 12};
    int b  = blockIdx.x >> 6;
    int lt = (blockIdx.x & 63) << 5;
    int tid = threadIdx.x;
    int d  = (tid & 127) << 2;
    int rh = tid >> 7;

    float cf[11][4];
#pragma unroll
    for (int c = 0; c < 4; c++) {
        int dd = d + c;
        float a0 = w0[dd * 3 + 0], a1 = w0[dd * 3 + 1], a2 = w0[dd * 3 + 2];
        float e0 = w1[dd * 5 + 0], e1 = w1[dd * 5 + 1], e2 = w1[dd * 5 + 2],
              e3 = w1[dd * 5 + 3], e4 = w1[dd * 5 + 4];
        float f0 = w2[dd * 7 + 0], f1 = w2[dd * 7 + 1], f2 = w2[dd * 7 + 2],
              f3 = w2[dd * 7 + 3], f4 = w2[dd * 7 + 4], f5 = w2[dd * 7 + 5],
              f6 = w2[dd * 7 + 6];
        cf[0][c]  = f0;            cf[1][c]  = f1;            cf[2][c]  = e0 + f2;
        cf[3][c]  = e1;            cf[4][c]  = a0;            cf[5][c]  = a1 + e2 + f3;
        cf[6][c]  = a2;            cf[7][c]  = e3;            cf[8][c]  = e4 + f4;
        cf[9][c]  = f5;            cf[10][c] = f6;
    }
    float aw[5]; int al[5];
#pragma unroll
    for (int j = 0; j < 5; j++) { aw[j] = g_w5[b * 5 + j]; al[j] = g_lag5[b * 5 + j]; }

    const float* xb = x + ((size_t)b * L_SEQ) * D_DIM;
    const bool interior = (lt >= 16) && (lt <= L_SEQ - 48);

    if (interior) {
#pragma unroll 1
        for (int lidx = rh; lidx < 32; lidx += 2) {
            int l = lt + lidx;
            float ax = 0.f, ay = 0.f, az = 0.f, aq = 0.f;
#pragma unroll
            for (int o = 0; o < 11; o++) {
                int ll = l + OFF[o];
                float4 xv = *(const float4*)(xb + (size_t)ll * D_DIM + d);
                ax += cf[o][0] * xv.x; ay += cf[o][1] * xv.y;
                az += cf[o][2] * xv.z; aq += cf[o][3] * xv.w;
            }
            float ux = 0.f, uy = 0.f, uz = 0.f, uq = 0.f;
#pragma unroll
            for (int j = 0; j < 5; j++) {
                int ll = l - al[j]; if (ll < 0) ll += L_SEQ;
                float4 xv = *(const float4*)(xb + (size_t)ll * D_DIM + d);
                ux += aw[j] * xv.x; uy += aw[j] * xv.y;
                uz += aw[j] * xv.z; uq += aw[j] * xv.w;
            }
            size_t row = (size_t)b * L_SEQ + l;
            *(uint2*)(g_ych + row * K_DIM + d) =
                make_uint2(pack_h2(ax, ay), pack_h2(az, aq));
            *(uint2*)(g_ych + row * K_DIM + 512 + d) =
                make_uint2(pack_h2(ux, uy), pack_h2(uz, uq));
        }
    } else {
#pragma unroll 1
        for (int lidx = rh; lidx < 32; lidx += 2) {
            int l = lt + lidx;
            float ax = 0.f, ay = 0.f, az = 0.f, aq = 0.f;
#pragma unroll
            for (int o = 0; o < 11; o++) {
                int ll = l + OFF[o];
                if (ll >= 0 && ll < L_SEQ) {
                    float4 xv = *(const float4*)(xb + (size_t)ll * D_DIM + d);
                    ax += cf[o][0] * xv.x; ay += cf[o][1] * xv.y;
                    az += cf[o][2] * xv.z; aq += cf[o][3] * xv.w;
                }
            }
            float ux = 0.f, uy = 0.f, uz = 0.f, uq = 0.f;
#pragma unroll
            for (int j = 0; j < 5; j++) {
                int ll = l - al[j]; if (ll < 0) ll += L_SEQ;
                float4 xv = *(const float4*)(xb + (size_t)ll * D_DIM + d);
                ux += aw[j] * xv.x; uy += aw[j] * xv.y;
                uz += aw[j] * xv.z; uq += aw[j] * xv.w;
            }
            size_t row = (size_t)b * L_SEQ + l;
            *(uint2*)(g_ych + row * K_DIM + d) =
                make_uint2(pack_h2(ax, ay), pack_h2(az, aq));
            *(uint2*)(g_ych + row * K_DIM + 512 + d) =
                make_uint2(pack_h2(ux, uy), pack_h2(uz, uq));
        }
    }
}

// =============== Kernel 4: fp16 mma.sync m16n8k16 GEMM, 128x128 block, 64x64 warp ===============
// BK=32, 4-stage cp.async pipeline, single __syncthreads per k-chunk, ldmatrix loads.
#define BK 32
#define ROW_H 20                        /* words per 32-half row (16 data + 4 pad) */
#define TILE_W (128 * ROW_H)            /* words per A or B tile: 2560 */
#define STG_W  (2 * TILE_W)
#define NSTAGE 4
#define GEMM_SMEM (NSTAGE * STG_W * 4)  /* 81920 B */

__global__ void __launch_bounds__(128, 2) gemm_fp16_kernel(
    const float* __restrict__ x, const float* __restrict__ bias, float* __restrict__ out)
{
    extern __shared__ uint32_t sm[];
    const int tid  = threadIdx.x;
    const int warp = tid >> 5, lane = tid & 31;
    const int gg = lane >> 2, tg = lane & 3;
    const int wm = (warp & 1) << 6;       // 2 warps along M
    const int wn = (warp >> 1) << 6;      // 2 warps along N
    const int n0 = (int)(blockIdx.x & 3) << 7;   // n fastest: A tile L2-shared by 4 CTAs
    const int m0 = (int)(blockIdx.x >> 2) << 7;

    const __half* Ag = g_ych + (size_t)m0 * K_DIM;
    const __half* Bg = g_wh  + (size_t)n0 * K_DIM;

    const uint32_t sbase = smem_to_u32(sm);
    const int r  = tid >> 2;              // staging row 0..31 (+32j)
    const int c4 = tid & 3;               // staging 16B-chunk 0..3

    // ldmatrix lane-address components
    const int rA = wm + (lane & 7) + ((lane >> 3) & 1) * 8;   // A row within tile
    const int wA = ((lane >> 4) & 1) * 4;                     // A k-chunk word
    const int rB = wn + (lane & 7);                           // B n-row
    const int wB = ((lane >> 3) & 1) * 4;                     // B k-chunk word (x2)

    float acc[4][8][4];
#pragma unroll
    for (int mi = 0; mi < 4; mi++)
#pragma unroll
        for (int ni = 0; ni < 8; ni++)
#pragma unroll
            for (int q = 0; q < 4; q++) acc[mi][ni][q] = 0.f;

    auto stage_load = [&](int kt, int s) {
        const __half* ag = Ag + kt * BK;
        const __half* bg = Bg + kt * BK;
        uint32_t sa = sbase + (uint32_t)(s * STG_W) * 4u;
        uint32_t sb = sa + TILE_W * 4u;
#pragma unroll
        for (int j = 0; j < 4; j++) {
            int rr = r + (j << 5);
            uint32_t off = (uint32_t)(rr * ROW_H + c4 * 4) * 4u;
            asm volatile("cp.async.cg.shared.global [%0], [%1], 16;"
                         :: "r"(sa + off), "l"(ag + (size_t)rr * K_DIM + c4 * 8));
            asm volatile("cp.async.cg.shared.global [%0], [%1], 16;"
                         :: "r"(sb + off), "l"(bg + (size_t)rr * K_DIM + c4 * 8));
        }
        asm volatile("cp.async.commit_group;" ::: "memory");
    };

    stage_load(0, 0); stage_load(1, 1); stage_load(2, 2);

#pragma unroll 1
    for (int kt = 0; kt < 32; kt++) {
        const int s = kt & 3;
        asm volatile("cp.async.wait_group 2;" ::: "memory");
        __syncthreads();
        // slot (kt+3)&3 == (kt-1)&3 : consumed in iteration kt-1; every warp passed
        // the barrier above after finishing that compute -> safe to refill now.
        if (kt + 3 < 32) stage_load(kt + 3, (kt + 3) & 3);
        else asm volatile("cp.async.commit_group;" ::: "memory");  // keep group count aligned

        const uint32_t abase = sbase + (uint32_t)(s * STG_W) * 4u;
        const uint32_t bbase = abase + TILE_W * 4u;
#pragma unroll
        for (int ks = 0; ks < 2; ks++) {
            uint32_t a[4][4], b[8][2];
#pragma unroll
            for (int mi = 0; mi < 4; mi++) {
                uint32_t ad = abase + (uint32_t)((rA + mi * 16) * ROW_H + wA + ks * 8) * 4u;
                asm volatile("ldmatrix.sync.aligned.m8n8.x4.shared.b16 {%0,%1,%2,%3}, [%4];"
                             : "=r"(a[mi][0]), "=r"(a[mi][1]), "=r"(a[mi][2]), "=r"(a[mi][3])
                             : "r"(ad));
            }
#pragma unroll
            for (int ni = 0; ni < 8; ni++) {
                uint32_t bd = bbase + (uint32_t)((rB + ni * 8) * ROW_H + wB + ks * 8) * 4u;
                asm volatile("ldmatrix.sync.aligned.m8n8.x2.shared.b16 {%0,%1}, [%2];"
                             : "=r"(b[ni][0]), "=r"(b[ni][1]) : "r"(bd));
            }
#pragma unroll
            for (int mi = 0; mi < 4; mi++)
#pragma unroll
                for (int ni = 0; ni < 8; ni++)
                    asm volatile(
                        "mma.sync.aligned.m16n8k16.row.col.f32.f16.f16.f32 "
                        "{%0,%1,%2,%3}, {%4,%5,%6,%7}, {%8,%9}, {%0,%1,%2,%3};\n"
                        : "+f"(acc[mi][ni][0]), "+f"(acc[mi][ni][1]),
                          "+f"(acc[mi][ni][2]), "+f"(acc[mi][ni][3])
                        : "r"(a[mi][0]), "r"(a[mi][1]), "r"(a[mi][2]), "r"(a[mi][3]),
                          "r"(b[ni][0]), "r"(b[ni][1]));
        }
    }

    // epilogue: h = gemm + bias + x
#pragma unroll
    for (int mi = 0; mi < 4; mi++) {
        int row = m0 + wm + (mi << 4) + gg;
#pragma unroll
        for (int ni = 0; ni < 8; ni++) {
            int col = n0 + wn + (ni << 3) + (tg << 1);
            float bz0 = bias[col], bz1 = bias[col + 1];
            float2 x0 = *(const float2*)(x + (size_t)row * N_DIM + col);
            float2 x1 = *(const float2*)(x + (size_t)(row + 8) * N_DIM + col);
            float2 o0 = make_float2(acc[mi][ni][0] + bz0 + x0.x, acc[mi][ni][1] + bz1 + x0.y);
            float2 o1 = make_float2(acc[mi][ni][2] + bz0 + x1.x, acc[mi][ni][3] + bz1 + x1.y);
            *(float2*)(out + (size_t)row * N_DIM + col)       = o0;
            *(float2*)(out + (size_t)(row + 8) * N_DIM + col) = o1;
        }
    }
}

// =============== Kernel 5: LayerNorm over D, in place on out ===============
__global__ __launch_bounds__(256) void ln_kernel(
    float* __restrict__ out, const float* __restrict__ gam, const float* __restrict__ bet)
{
    int row  = blockIdx.x * 8 + (threadIdx.x >> 5);
    int lane = threadIdx.x & 31;
    float4* o4 = (float4*)(out + (size_t)row * D_DIM);
    float4 v[4];
    float s = 0.f, s2 = 0.f;
#pragma unroll
    for (int q = 0; q < 4; q++) {
        v[q] = o4[q * 32 + lane];
        s  += v[q].x + v[q].y + v[q].z + v[q].w;
        s2 += v[q].x * v[q].x + v[q].y * v[q].y + v[q].z * v[q].z + v[q].w * v[q].w;
    }
#pragma unroll
    for (int o = 16; o; o >>= 1) {
        s  += __shfl_xor_sync(0xffffffffu, s, o);
        s2 += __shfl_xor_sync(0xffffffffu, s2, o);
    }
    float mu  = s * (1.0f / 512.0f);
    float var = s2 * (1.0f / 512.0f) - mu * mu;
    float inv = rsqrtf(var + 1e-5f);
    const float4* g4 = (const float4*)gam;
    const float4* b4 = (const float4*)bet;
#pragma unroll
    for (int q = 0; q < 4; q++) {
        float4 gv = g4[q * 32 + lane], bv = b4[q * 32 + lane];
        float4 r;
        r.x = (v[q].x - mu) * inv * gv.x + bv.x;
        r.y = (v[q].y - mu) * inv * gv.y + bv.y;
        r.z = (v[q].z - mu) * inv * gv.z + bv.z;
        r.w = (v[q].w - mu) * inv * gv.w + bv.w;
        o4[q * 32 + lane] = r;
    }
}

// ============================== launch ==============================
extern "C" void kernel_launch(void* const* d_in, const int* in_sizes, int n_in,
                              void* d_out, int out_size) {
    const float* x   = (const float*)d_in[0];
    const float* cw0 = (const float*)d_in[1];
    const float* cw1 = (const float*)d_in[2];
    const float* cw2 = (const float*)d_in[3];
    const float* pw  = (const float*)d_in[4];
    const float* pb  = (const float*)d_in[5];
    const float* lng = (const float*)d_in[6];
    const float* lnb = (const float*)d_in[7];
    float* out = (float*)d_out;

    cudaFuncSetAttribute(gemm_fp16_kernel,
                         cudaFuncAttributeMaxDynamicSharedMemorySize, GEMM_SMEM);

    mean_kernel<<<M_ROWS / 8, 256>>>(x);
    scores_kernel<<<B_BATCH, 256>>>();
    whalf_kernel<<<(N_DIM * K_DIM) / 1024, 256>>>(pw);
    ycat_kernel<<<B_BATCH * (L_SEQ / 32), 256>>>(x, cw0, cw1, cw2);
    gemm_fp16_kernel<<<(M_ROWS / 128) * (N_DIM / 128), 128, GEMM_SMEM>>>(x, pb, out);
    ln_kernel<<<M_ROWS / 8, 256>>>(out, lng, lnb);
}

// round 17
// speedup vs baseline: 1.8510x; 1.0419x over previous
#include <cuda_runtime.h>
#include <cuda_fp16.h>
#include <cstdint>

#define L_SEQ   2048
#define D_DIM   512
#define B_BATCH 32
#define M_ROWS  (B_BATCH * L_SEQ)   /* 65536 */
#define K_DIM   1024
#define N_DIM   512

// ---------------- scratch (static device globals: no allocation) ----------------
__device__ __half g_ych[(size_t)M_ROWS * K_DIM];   // 128 MiB: [y_conv | y_auto] in fp16
__device__ __half g_wh[(size_t)N_DIM * K_DIM];     // fp16 proj_w
__device__ float g_xm[M_ROWS];
__device__ float g_w5[B_BATCH * 5];
__device__ int   g_lag5[B_BATCH * 5];

__device__ __forceinline__ uint32_t smem_to_u32(const void* p) {
    uint32_t a;
    asm("{ .reg .u64 t; cvta.to.shared.u64 t, %1; cvt.u32.u64 %0, t; }" : "=r"(a) : "l"(p));
    return a;
}
__device__ __forceinline__ uint32_t pack_h2(float a, float b) {
    __half2 h = __floats2half2_rn(a, b);
    return *(uint32_t*)&h;
}

// Candidate lag i of np.linspace(1,168,32).astype(int64)
__device__ __forceinline__ int lag_of(int i) {
    if (i == 31) return 168;
    return (int)(1.0 + (double)i * (167.0 / 31.0));
}

// =================== Kernel 1: xm[b,l] = mean_d x[b,l,d] ===================
__global__ __launch_bounds__(256) void mean_kernel(const float* __restrict__ x) {
    int row  = blockIdx.x * 8 + (threadIdx.x >> 5);
    int lane = threadIdx.x & 31;
    const float4* xr = (const float4*)(x + (size_t)row * D_DIM);
    float s = 0.f;
#pragma unroll
    for (int q = 0; q < 4; q++) {
        float4 v = xr[q * 32 + lane];
        s += v.x + v.y + v.z + v.w;
    }
#pragma unroll
    for (int o = 16; o; o >>= 1) s += __shfl_down_sync(0xffffffffu, s, o);
    if (lane == 0) g_xm[row] = s * (1.0f / 512.0f);
}

// =============== Kernel 2: per-batch lag scores, top-5 weights ===============
__global__ __launch_bounds__(256) void scores_kernel() {
    __shared__ float s[L_SEQ];
    __shared__ float sc[32];
    int b = blockIdx.x, tid = threadIdx.x;
    for (int i = tid; i < L_SEQ; i += 256) s[i] = g_xm[b * L_SEQ + i];
    __syncthreads();
    int warp = tid >> 5, lane = tid & 31;
#pragma unroll
    for (int j = 0; j < 4; j++) {
        int li = warp * 4 + j;
        int lag = lag_of(li);
        float p = 0.f;
        for (int t = lane; t < L_SEQ - lag; t += 32) p += s[t] * s[t + lag];
#pragma unroll
        for (int o = 16; o; o >>= 1) p += __shfl_down_sync(0xffffffffu, p, o);
        if (lane == 0) sc[li] = p / (float)(L_SEQ - lag);
    }
    __syncthreads();
    if (tid == 0) {
        bool used[32];
        for (int i = 0; i < 32; i++) used[i] = false;
        float vals[5]; int idx[5];
        for (int p = 0; p < 5; p++) {
            float best = -3.4e38f; int bi = 0;
            for (int i = 0; i < 32; i++)
                if (!used[i] && sc[i] > best) { best = sc[i]; bi = i; }
            used[bi] = true; vals[p] = best; idx[p] = bi;
        }
        float denom = vals[0] + vals[1] + vals[2] + vals[3] + vals[4] + 1e-6f;
        for (int p = 0; p < 5; p++) {
            g_w5[b * 5 + p]   = vals[p] / denom;
            g_lag5[b * 5 + p] = lag_of(idx[p]);
        }
    }
}

// =============== Kernel 2b: proj_w -> fp16 ===============
__global__ __launch_bounds__(256) void whalf_kernel(const float* __restrict__ w) {
    size_t i = (size_t)blockIdx.x * 1024 + (size_t)threadIdx.x * 4;
    float4 v = *(const float4*)(w + i);
    *(uint2*)(g_wh + i) = make_uint2(pack_h2(v.x, v.y), pack_h2(v.z, v.w));
}

// =============== Kernel 3: build ycat = [y_conv | y_auto] (fp16) ===============
// Interior path: 4 consecutive rows per group share the contiguous conv window
// [-12,+15] -> 28 loads serve 44 tap-reads (25% fewer loads, higher MLP).
__global__ __launch_bounds__(256, 2) void ycat_kernel(
    const float* __restrict__ x,  const float* __restrict__ w0,
    const float* __restrict__ w1, const float* __restrict__ w2)
{
    const int OFF[11] = {-12, -8, -4, -2, -1, 0, 1, 2, 4, 8, 12};
    // tap index by (offset+12), -1 if not a tap
    const int TAPI[25] = { 0, -1, -1, -1,  1, -1, -1, -1,  2, -1,
                           3,  4,  5,  6,  7, -1,  8, -1, -1, -1,
                           9, -1, -1, -1, 10 };
    int b  = blockIdx.x >> 6;
    int lt = (blockIdx.x & 63) << 5;
    int tid = threadIdx.x;
    int d  = (tid & 127) << 2;
    int rh = tid >> 7;

    float cf[11][4];
#pragma unroll
    for (int c = 0; c < 4; c++) {
        int dd = d + c;
        float a0 = w0[dd * 3 + 0], a1 = w0[dd * 3 + 1], a2 = w0[dd * 3 + 2];
        float e0 = w1[dd * 5 + 0], e1 = w1[dd * 5 + 1], e2 = w1[dd * 5 + 2],
              e3 = w1[dd * 5 + 3], e4 = w1[dd * 5 + 4];
        float f0 = w2[dd * 7 + 0], f1 = w2[dd * 7 + 1], f2 = w2[dd * 7 + 2],
              f3 = w2[dd * 7 + 3], f4 = w2[dd * 7 + 4], f5 = w2[dd * 7 + 5],
              f6 = w2[dd * 7 + 6];
        cf[0][c]  = f0;            cf[1][c]  = f1;            cf[2][c]  = e0 + f2;
        cf[3][c]  = e1;            cf[4][c]  = a0;            cf[5][c]  = a1 + e2 + f3;
        cf[6][c]  = a2;            cf[7][c]  = e3;            cf[8][c]  = e4 + f4;
        cf[9][c]  = f5;            cf[10][c] = f6;
    }
    float aw[5]; int al[5];
#pragma unroll
    for (int j = 0; j < 5; j++) { aw[j] = g_w5[b * 5 + j]; al[j] = g_lag5[b * 5 + j]; }

    const float* xb = x + ((size_t)b * L_SEQ) * D_DIM;
    // interior needs rows [lt-12, lt+31+15] in range
    const bool interior = (lt >= 16) && (lt + 46 <= L_SEQ - 1);

    if (interior) {
        int l0 = lt + rh * 16;
#pragma unroll 1
        for (int g = 0; g < 4; g++, l0 += 4) {
            float ac[4][4];
#pragma unroll
            for (int r = 0; r < 4; r++)
#pragma unroll
                for (int c = 0; c < 4; c++) ac[r][c] = 0.f;
            // shared contiguous conv window
#pragma unroll
            for (int u = -12; u <= 15; u++) {
                float4 xv = *(const float4*)(xb + (size_t)(l0 + u) * D_DIM + d);
#pragma unroll
                for (int r = 0; r < 4; r++) {
                    int um = u - r;
                    if (um >= -12 && um <= 12) {
                        int ti = TAPI[um + 12];
                        if (ti >= 0) {
                            ac[r][0] += cf[ti][0] * xv.x;
                            ac[r][1] += cf[ti][1] * xv.y;
                            ac[r][2] += cf[ti][2] * xv.z;
                            ac[r][3] += cf[ti][3] * xv.w;
                        }
                    }
                }
            }
            float au[4][4];
#pragma unroll
            for (int r = 0; r < 4; r++)
#pragma unroll
                for (int c = 0; c < 4; c++) au[r][c] = 0.f;
#pragma unroll
            for (int j = 0; j < 5; j++) {
#pragma unroll
                for (int r = 0; r < 4; r++) {
                    int ll = l0 + r - al[j]; if (ll < 0) ll += L_SEQ;
                    float4 xv = *(const float4*)(xb + (size_t)ll * D_DIM + d);
                    au[r][0] += aw[j] * xv.x; au[r][1] += aw[j] * xv.y;
                    au[r][2] += aw[j] * xv.z; au[r][3] += aw[j] * xv.w;
                }
            }
#pragma unroll
            for (int r = 0; r < 4; r++) {
                size_t row = (size_t)b * L_SEQ + (l0 + r);
                *(uint2*)(g_ych + row * K_DIM + d) =
                    make_uint2(pack_h2(ac[r][0], ac[r][1]), pack_h2(ac[r][2], ac[r][3]));
                *(uint2*)(g_ych + row * K_DIM + 512 + d) =
                    make_uint2(pack_h2(au[r][0], au[r][1]), pack_h2(au[r][2], au[r][3]));
            }
        }
    } else {
#pragma unroll 1
        for (int lidx = rh; lidx < 32; lidx += 2) {
            int l = lt + lidx;
            float ax = 0.f, ay = 0.f, az = 0.f, aq = 0.f;
#pragma unroll
            for (int o = 0; o < 11; o++) {
                int ll = l + OFF[o];
                if (ll >= 0 && ll < L_SEQ) {
                    float4 xv = *(const float4*)(xb + (size_t)ll * D_DIM + d);
                    ax += cf[o][0] * xv.x; ay += cf[o][1] * xv.y;
                    az += cf[o][2] * xv.z; aq += cf[o][3] * xv.w;
                }
            }
            float ux = 0.f, uy = 0.f, uz = 0.f, uq = 0.f;
#pragma unroll
            for (int j = 0; j < 5; j++) {
                int ll = l - al[j]; if (ll < 0) ll += L_SEQ;
                float4 xv = *(const float4*)(xb + (size_t)ll * D_DIM + d);
                ux += aw[j] * xv.x; uy += aw[j] * xv.y;
                uz += aw[j] * xv.z; uq += aw[j] * xv.w;
            }
            size_t row = (size_t)b * L_SEQ + l;
            *(uint2*)(g_ych + row * K_DIM + d) =
                make_uint2(pack_h2(ax, ay), pack_h2(az, aq));
            *(uint2*)(g_ych + row * K_DIM + 512 + d) =
                make_uint2(pack_h2(ux, uy), pack_h2(uz, uq));
        }
    }
}

// =============== Kernel 4: fp16 mma.sync m16n8k16 GEMM, 128x128 block, 64x64 warp ===============
// BK=32, 4-stage cp.async pipeline, single __syncthreads per k-chunk, ldmatrix loads.
#define BK 32
#define ROW_H 20                        /* words per 32-half row (16 data + 4 pad) */
#define TILE_W (128 * ROW_H)            /* words per A or B tile: 2560 */
#define STG_W  (2 * TILE_W)
#define NSTAGE 4
#define GEMM_SMEM (NSTAGE * STG_W * 4)  /* 81920 B */

__global__ void __launch_bounds__(128, 2) gemm_fp16_kernel(
    const float* __restrict__ x, const float* __restrict__ bias, float* __restrict__ out)
{
    extern __shared__ uint32_t sm[];
    const int tid  = threadIdx.x;
    const int warp = tid >> 5, lane = tid & 31;
    const int gg = lane >> 2, tg = lane & 3;
    const int wm = (warp & 1) << 6;       // 2 warps along M
    const int wn = (warp >> 1) << 6;      // 2 warps along N
    const int n0 = (int)(blockIdx.x & 3) << 7;   // n fastest: A tile L2-shared by 4 CTAs
    const int m0 = (int)(blockIdx.x >> 2) << 7;

    const __half* Ag = g_ych + (size_t)m0 * K_DIM;
    const __half* Bg = g_wh  + (size_t)n0 * K_DIM;

    const uint32_t sbase = smem_to_u32(sm);
    const int r  = tid >> 2;              // staging row 0..31 (+32j)
    const int c4 = tid & 3;               // staging 16B-chunk 0..3

    // ldmatrix lane-address components
    const int rA = wm + (lane & 7) + ((lane >> 3) & 1) * 8;   // A row within tile
    const int wA = ((lane >> 4) & 1) * 4;                     // A k-chunk word
    const int rB = wn + (lane & 7);                           // B n-row
    const int wB = ((lane >> 3) & 1) * 4;                     // B k-chunk word (x2)

    float acc[4][8][4];
#pragma unroll
    for (int mi = 0; mi < 4; mi++)
#pragma unroll
        for (int ni = 0; ni < 8; ni++)
#pragma unroll
            for (int q = 0; q < 4; q++) acc[mi][ni][q] = 0.f;

    auto stage_load = [&](int kt, int s) {
        const __half* ag = Ag + kt * BK;
        const __half* bg = Bg + kt * BK;
        uint32_t sa = sbase + (uint32_t)(s * STG_W) * 4u;
        uint32_t sb = sa + TILE_W * 4u;
#pragma unroll
        for (int j = 0; j < 4; j++) {
            int rr = r + (j << 5);
            uint32_t off = (uint32_t)(rr * ROW_H + c4 * 4) * 4u;
            asm volatile("cp.async.cg.shared.global [%0], [%1], 16;"
                         :: "r"(sa + off), "l"(ag + (size_t)rr * K_DIM + c4 * 8));
            asm volatile("cp.async.cg.shared.global [%0], [%1], 16;"
                         :: "r"(sb + off), "l"(bg + (size_t)rr * K_DIM + c4 * 8));
        }
        asm volatile("cp.async.commit_group;" ::: "memory");
    };

    stage_load(0, 0); stage_load(1, 1); stage_load(2, 2);

#pragma unroll 1
    for (int kt = 0; kt < 32; kt++) {
        const int s = kt & 3;
        asm volatile("cp.async.wait_group 2;" ::: "memory");
        __syncthreads();
        // slot (kt+3)&3 == (kt-1)&3 : consumed in iteration kt-1; every warp passed
        // the barrier above after finishing that compute -> safe to refill now.
        if (kt + 3 < 32) stage_load(kt + 3, (kt + 3) & 3);
        else asm volatile("cp.async.commit_group;" ::: "memory");  // keep group count aligned

        const uint32_t abase = sbase + (uint32_t)(s * STG_W) * 4u;
        const uint32_t bbase = abase + TILE_W * 4u;
#pragma unroll
        for (int ks = 0; ks < 2; ks++) {
            uint32_t a[4][4], b[8][2];
#pragma unroll
            for (int mi = 0; mi < 4; mi++) {
                uint32_t ad = abase + (uint32_t)((rA + mi * 16) * ROW_H + wA + ks * 8) * 4u;
                asm volatile("ldmatrix.sync.aligned.m8n8.x4.shared.b16 {%0,%1,%2,%3}, [%4];"
                             : "=r"(a[mi][0]), "=r"(a[mi][1]), "=r"(a[mi][2]), "=r"(a[mi][3])
                             : "r"(ad));
            }
#pragma unroll
            for (int ni = 0; ni < 8; ni++) {
                uint32_t bd = bbase + (uint32_t)((rB + ni * 8) * ROW_H + wB + ks * 8) * 4u;
                asm volatile("ldmatrix.sync.aligned.m8n8.x2.shared.b16 {%0,%1}, [%2];"
                             : "=r"(b[ni][0]), "=r"(b[ni][1]) : "r"(bd));
            }
#pragma unroll
            for (int mi = 0; mi < 4; mi++)
#pragma unroll
                for (int ni = 0; ni < 8; ni++)
                    asm volatile(
                        "mma.sync.aligned.m16n8k16.row.col.f32.f16.f16.f32 "
                        "{%0,%1,%2,%3}, {%4,%5,%6,%7}, {%8,%9}, {%0,%1,%2,%3};\n"
                        : "+f"(acc[mi][ni][0]), "+f"(acc[mi][ni][1]),
                          "+f"(acc[mi][ni][2]), "+f"(acc[mi][ni][3])
                        : "r"(a[mi][0]), "r"(a[mi][1]), "r"(a[mi][2]), "r"(a[mi][3]),
                          "r"(b[ni][0]), "r"(b[ni][1]));
        }
    }

    // epilogue: h = gemm + bias + x
#pragma unroll
    for (int mi = 0; mi < 4; mi++) {
        int row = m0 + wm + (mi << 4) + gg;
#pragma unroll
        for (int ni = 0; ni < 8; ni++) {
            int col = n0 + wn + (ni << 3) + (tg << 1);
            float bz0 = bias[col], bz1 = bias[col + 1];
            float2 x0 = *(const float2*)(x + (size_t)row * N_DIM + col);
            float2 x1 = *(const float2*)(x + (size_t)(row + 8) * N_DIM + col);
            float2 o0 = make_float2(acc[mi][ni][0] + bz0 + x0.x, acc[mi][ni][1] + bz1 + x0.y);
            float2 o1 = make_float2(acc[mi][ni][2] + bz0 + x1.x, acc[mi][ni][3] + bz1 + x1.y);
            *(float2*)(out + (size_t)row * N_DIM + col)       = o0;
            *(float2*)(out + (size_t)(row + 8) * N_DIM + col) = o1;
        }
    }
}

// =============== Kernel 5: LayerNorm over D, in place on out ===============
__global__ __launch_bounds__(256) void ln_kernel(
    float* __restrict__ out, const float* __restrict__ gam, const float* __restrict__ bet)
{
    int row  = blockIdx.x * 8 + (threadIdx.x >> 5);
    int lane = threadIdx.x & 31;
    float4* o4 = (float4*)(out + (size_t)row * D_DIM);
    float4 v[4];
    float s = 0.f, s2 = 0.f;
#pragma unroll
    for (int q = 0; q < 4; q++) {
        v[q] = o4[q * 32 + lane];
        s  += v[q].x + v[q].y + v[q].z + v[q].w;
        s2 += v[q].x * v[q].x + v[q].y * v[q].y + v[q].z * v[q].z + v[q].w * v[q].w;
    }
#pragma unroll
    for (int o = 16; o; o >>= 1) {
        s  += __shfl_xor_sync(0xffffffffu, s, o);
        s2 += __shfl_xor_sync(0xffffffffu, s2, o);
    }
    float mu  = s * (1.0f / 512.0f);
    float var = s2 * (1.0f / 512.0f) - mu * mu;
    float inv = rsqrtf(var + 1e-5f);
    const float4* g4 = (const float4*)gam;
    const float4* b4 = (const float4*)bet;
#pragma unroll
    for (int q = 0; q < 4; q++) {
        float4 gv = g4[q * 32 + lane], bv = b4[q * 32 + lane];
        float4 r;
        r.x = (v[q].x - mu) * inv * gv.x + bv.x;
        r.y = (v[q].y - mu) * inv * gv.y + bv.y;
        r.z = (v[q].z - mu) * inv * gv.z + bv.z;
        r.w = (v[q].w - mu) * inv * gv.w + bv.w;
        o4[q * 32 + lane] = r;
    }
}

// ============================== launch ==============================
extern "C" void kernel_launch(void* const* d_in, const int* in_sizes, int n_in,
                              void* d_out, int out_size) {
    const float* x   = (const float*)d_in[0];
    const float* cw0 = (const float*)d_in[1];
    const float* cw1 = (const float*)d_in[2];
    const float* cw2 = (const float*)d_in[3];
    const float* pw  = (const float*)d_in[4];
    const float* pb  = (const float*)d_in[5];
    const float* lng = (const float*)d_in[6];
    const float* lnb = (const float*)d_in[7];
    float* out = (float*)d_out;

    cudaFuncSetAttribute(gemm_fp16_kernel,
                         cudaFuncAttributeMaxDynamicSharedMemorySize, GEMM_SMEM);

    mean_kernel<<<M_ROWS / 8, 256>>>(x);
    scores_kernel<<<B_BATCH, 256>>>();
    whalf_kernel<<<(N_DIM * K_DIM) / 1024, 256>>>(pw);
    ycat_kernel<<<B_BATCH * (L_SEQ / 32), 256>>>(x, cw0, cw1, cw2);
    gemm_fp16_kernel<<<(M_ROWS / 128) * (N_DIM / 128), 128, GEMM_SMEM>>>(x, pb, out);
    ln_kernel<<<M_ROWS / 8, 256>>>(out, lng, lnb);
}